// round 16
// baseline (speedup 1.0000x reference)
#include <cuda_runtime.h>
#include <math.h>
#include <stdint.h>

#define BB    1024     // batch rows
#define NN    8192     // samples per row
#define MM2   900      // parity-fold period
#define MM3   486      // reflection-folded m range (451 used, padded to 9*54)
#define NB    140      // bpm bins
#define NBP   144      // padded bins
#define NCH   9        // m-chunks
#define CHM   54       // m per chunk (9*54 = 486)
#define SLAB  9        // m per smem slab (6 steps)

// ---------------- device scratch ----------------
__device__ float4 d_fold[(size_t)BB * MM3];             // (ve,ue,vo,uo) per (row,m)
__device__ float2 d_part[(size_t)BB * NCH * NBP];       // [row][chunk][bin] (S,C)
__device__ float  d_tl[BB];
__device__ float  d_fl[BB];

typedef unsigned long long ull;

// ---------------- f32x2 helpers ----------------
__device__ __forceinline__ ull pk2(float lo, float hi) {
    ull r;
    asm("mov.b64 %0, {%1, %2};" : "=l"(r) : "f"(lo), "f"(hi));
    return r;
}
__device__ __forceinline__ void upk2(float& lo, float& hi, ull v) {
    asm("mov.b64 {%0, %1}, %2;" : "=f"(lo), "=f"(hi) : "l"(v));
}
__device__ __forceinline__ void fma2(ull& d, ull a, ull b) {
    asm("fma.rn.f32x2 %0, %1, %2, %0;" : "+l"(d) : "l"(a), "l"(b));
}
__device__ __forceinline__ ull add2(ull a, ull b) {
    ull r;
    asm("add.rn.f32x2 %0, %1, %2;" : "=l"(r) : "l"(a), "l"(b));
    return r;
}
__device__ __forceinline__ ull mul2(ull a, ull b) {
    ull r;
    asm("mul.rn.f32x2 %0, %1, %2;" : "=l"(r) : "l"(a), "l"(b));
    return r;
}
__device__ __forceinline__ float sum2(ull v) {
    float lo, hi; upk2(lo, hi, v); return lo + hi;
}

// ---------------- warp helpers ----------------
__device__ __forceinline__ float wsum(float v) {
    #pragma unroll
    for (int o = 16; o; o >>= 1) v += __shfl_down_sync(0xffffffffu, v, o);
    return v;
}
__device__ __forceinline__ float wallsum(float v) {
    #pragma unroll
    for (int o = 16; o; o >>= 1) v += __shfl_xor_sync(0xffffffffu, v, o);
    return v;
}
__device__ __forceinline__ float wallmax(float v) {
    #pragma unroll
    for (int o = 16; o; o >>= 1) v = fmaxf(v, __shfl_xor_sync(0xffffffffu, v, o));
    return v;
}

// ---------------- K1: pearson + parity fold, float2/thread, high-occ ---------
// thread t<450 owns fold-bins {2t, 2t+1}; float2 index q = t + 450*j
__global__ void __launch_bounds__(512, 3) k_fold(const float* __restrict__ x,
                                                 const float* __restrict__ y) {
    __shared__ float sge[MM2];
    __shared__ float sgo[MM2];
    __shared__ float red[16][5];
    int b = blockIdx.x;
    int tid = threadIdx.x;
    int lane = tid & 31, warp = tid >> 5;

    const float2* xr = (const float2*)(x + (size_t)b * NN);
    const float2* yr = (const float2*)(y + (size_t)b * NN);
    const float W = 3.8349520e-4f;          // pi/8191
    const ull NEG1 = pk2(-1.f, -1.f);

    ull ax = 0, ay = 0, axx = 0, ayy = 0, axy = 0;
    ull ge = 0, go = 0;

    if (tid < 450) {
        #pragma unroll
        for (int j = 0; j < 10; j++) {
            int q = tid + 450 * j;
            if (j < 9 || q < 4096) {
                float2 xv = xr[q];
                float2 yv = yr[q];
                ull xp = pk2(xv.x, xv.y), yp = pk2(yv.x, yv.y);
                ax = add2(ax, xp);  ay = add2(ay, yp);
                fma2(axx, xp, xp);  fma2(ayy, yp, yp);  fma2(axy, xp, yp);

                int n = 2 * q;
                float s0 = __sinf((float)(n)     * W);
                float s1 = __sinf((float)(n + 1) * W);
                ull sp = pk2(s0, s1);
                sp = mul2(sp, sp);                 // sin^2 (hann)
                ull h = mul2(xp, sp);
                ge = add2(ge, h);
                if (j & 1) fma2(go, h, NEG1);
                else       go = add2(go, h);
            }
        }
        float g0, g1, o0, o1;
        upk2(g0, g1, ge);
        upk2(o0, o1, go);
        sge[2 * tid]     = g0;  sgo[2 * tid]     = o0;
        sge[2 * tid + 1] = g1;  sgo[2 * tid + 1] = o1;
    }
    __syncthreads();

    // reflection combos: even f: (v,u)=(g[m]-g[900-m], g[m]+g[900-m])
    //                    odd  f: (v,u)=(g[m]+g[900-m], g[m]-g[900-m])
    for (int m = tid; m < MM3; m += 512) {
        float4 o;
        if (m == 0) {
            o = make_float4(sge[0], sge[0], sgo[0], sgo[0]);
        } else if (m < 450) {
            float a = sge[m], bb2 = sge[900 - m];
            float c = sgo[m], d  = sgo[900 - m];
            o = make_float4(a - bb2, a + bb2, c + d, c - d);
        } else if (m == 450) {
            o = make_float4(sge[450], sge[450], sgo[450], sgo[450]);
        } else {
            o = make_float4(0.f, 0.f, 0.f, 0.f);
        }
        d_fold[(size_t)b * MM3 + m] = o;
    }

    float sx = sum2(ax);
    float sy = sum2(ay);
    float sxx = sum2(axx);
    float syy = sum2(ayy);
    float sxy = sum2(axy);

    sx = wsum(sx); sy = wsum(sy); sxy = wsum(sxy); sxx = wsum(sxx); syy = wsum(syy);
    if (lane == 0) { red[warp][0]=sx; red[warp][1]=sy; red[warp][2]=sxy; red[warp][3]=sxx; red[warp][4]=syy; }
    __syncthreads();
    if (tid == 0) {
        double SX=0, SY=0, SXY=0, SXX=0, SYY=0;
        #pragma unroll
        for (int w = 0; w < 16; w++) {
            SX += red[w][0]; SY += red[w][1]; SXY += red[w][2];
            SXX += red[w][3]; SYY += red[w][4];
        }
        double num = (double)NN * SXY - SX * SY;
        double den = sqrt(((double)NN * SXX - SX * SX) * ((double)NN * SYY - SY * SY));
        d_tl[b] = (float)(1.0 - num / den);
    }
}

// ---------------- K2: reflected parity NUDFT (unchanged) ---------------------
__global__ void __launch_bounds__(288, 2) k_dft() {
    __shared__ float sTab[SLAB * 2 * NBP];
    __shared__ ull   sGE[SLAB][32];
    __shared__ ull   sGO[SLAB][32];

    int tile  = blockIdx.x;
    int chunk = blockIdx.y;
    int tid = threadIdx.x;
    int tx = tid % 36;
    int ty = tid / 36;

    int rowBase = tile * 32;
    int mBase = chunk * CHM;

    int bk  = tid % NBP;
    int grp = tid / NBP;
    int freq = 40 + bk;

    ull acc[4][4] = {};
    const ull* gbase = (tx & 1) ? &sGO[0][0] : &sGE[0][0];
    const float ASCALE = 3.4906585e-3f;

    for (int step = 0; step < CHM / SLAB; step++) {
        int m0 = mBase + step * SLAB;
        __syncthreads();
        #pragma unroll
        for (int i = 0; i < 5; i++) {
            int mi = grp * 5 + i;
            if (mi < SLAB) {
                float s = 0.f, c = 0.f;
                if (bk < NB) {
                    int r = (freq * (m0 + mi)) % 1800;
                    if (r >= 900) r -= 1800;
                    __sincosf((float)r * ASCALE, &s, &c);
                }
                sTab[mi * (2 * NBP) + 2 * bk]     = s;
                sTab[mi * (2 * NBP) + 2 * bk + 1] = c;
            }
        }
        {
            int r = tid & 31, mi = tid >> 5;
            float4 v = d_fold[(size_t)(rowBase + r) * MM3 + m0 + mi];
            sGE[mi][r] = pk2(v.x, v.y);
            sGO[mi][r] = pk2(v.z, v.w);
        }
        __syncthreads();

        #pragma unroll
        for (int mi = 0; mi < SLAB; mi++) {
            const ull* gq = gbase + mi * 32 + 4 * ty;
            ull g0 = gq[0], g1 = gq[1], g2 = gq[2], g3 = gq[3];
            const ull* trow = (const ull*)&sTab[mi * (2 * NBP)];
            ull p0 = trow[tx];
            ull p1 = trow[tx + 36];
            ull p2 = trow[tx + 72];
            ull p3 = trow[tx + 108];
            fma2(acc[0][0], g0, p0); fma2(acc[0][1], g0, p1);
            fma2(acc[0][2], g0, p2); fma2(acc[0][3], g0, p3);
            fma2(acc[1][0], g1, p0); fma2(acc[1][1], g1, p1);
            fma2(acc[1][2], g1, p2); fma2(acc[1][3], g1, p3);
            fma2(acc[2][0], g2, p0); fma2(acc[2][1], g2, p1);
            fma2(acc[2][2], g2, p2); fma2(acc[2][3], g2, p3);
            fma2(acc[3][0], g3, p0); fma2(acc[3][1], g3, p1);
            fma2(acc[3][2], g3, p2); fma2(acc[3][3], g3, p3);
        }
    }

    #pragma unroll
    for (int r = 0; r < 4; r++) {
        int row = rowBase + 4 * ty + r;
        ull* dst = (ull*)(d_part + ((size_t)row * NCH + chunk) * NBP);
        dst[tx]       = acc[r][0];
        dst[tx + 36]  = acc[r][1];
        dst[tx + 72]  = acc[r][2];
        dst[tx + 108] = acc[r][3];
    }
}

// ---------------- K3: one block per row; thread = bin (R14 verbatim) ---------
#define LT 160   // threads (5 warps); bins 0..143 active
__global__ void __launch_bounds__(LT) k_loss(const int* __restrict__ hr) {
    __shared__ float sh[8];
    __shared__ float shH;
    int tid = threadIdx.x;
    int lane = tid & 31, warp = tid >> 5;
    int row = blockIdx.x;
    bool valid = tid < NB;

    float s = 0.f, c = 0.f;
    if (valid) {
        const float2* pr = d_part + (size_t)row * NCH * NBP + tid;
        #pragma unroll
        for (int ch = 0; ch < NCH; ch++) {
            float2 v = pr[ch * NBP];
            s += v.x; c += v.y;
        }
    }
    float ca = valid ? (s * s + c * c) : 0.f;

    float v = wallsum(ca);
    if (lane == 0) sh[warp] = v;
    __syncthreads();
    float tot = sh[0] + sh[1] + sh[2] + sh[3] + sh[4];
    __syncthreads();

    float logit = ca / tot;

    v = wallmax(valid ? logit : -1e30f);
    if (lane == 0) sh[warp] = v;
    __syncthreads();
    float mx = fmaxf(fmaxf(fmaxf(sh[0], sh[1]), fmaxf(sh[2], sh[3])), sh[4]);
    __syncthreads();

    v = wallsum(valid ? expf(logit - mx) : 0.f);
    if (lane == 0) sh[warp] = v;
    __syncthreads();
    float lse = mx + logf(sh[0] + sh[1] + sh[2] + sh[3] + sh[4]);

    int h = hr[row];
    if (tid == h) shH = logit;
    __syncthreads();
    float ce = lse - shH;
    __syncthreads();

    float klc = 0.f;
    if (valid) {
        float dd = (float)tid - (float)h;
        float t = expf(-0.5f * dd * dd) * 0.3989422804014327f;
        t = fmaxf(t, 1e-15f);
        klc = expf(t) * (t - (logit - lse));
    }
    v = wallsum(klc);
    if (lane == 0) sh[warp] = v;
    __syncthreads();
    if (tid == 0) d_fl[row] = ce + (sh[0] + sh[1] + sh[2] + sh[3] + sh[4]) / (float)NB;
}

// ---------------- K4: final scalar (R14 verbatim) ----------------
__global__ void __launch_bounds__(1024) k_final(const int* __restrict__ epoch_p,
                                                float* __restrict__ out) {
    __shared__ float r1[32], r2[32];
    int tid = threadIdx.x, lane = tid & 31, warp = tid >> 5;
    float a = d_tl[tid], c = d_fl[tid];
    a = wsum(a); c = wsum(c);
    if (lane == 0) { r1[warp] = a; r2[warp] = c; }
    __syncthreads();
    if (warp == 0) {
        a = wsum(r1[lane]);
        c = wsum(r2[lane]);
        if (lane == 0) {
            float tl = a / (float)BB;
            float fl = c / (float)BB;
            int epoch = epoch_p[0];
            float alpha, beta;
            if (epoch > 25) { alpha = 0.05f; beta = 2.0f; }
            else {
                float e = (float)epoch * 0.04f;       // epoch/25
                alpha = 0.1f * exp2f(-e);
                beta  = exp2f(e);
            }
            out[0] = alpha * tl + beta * fl;
        }
    }
}

// ---------------- launch ----------------
extern "C" void kernel_launch(void* const* d_in, const int* in_sizes, int n_in,
                              void* d_out, int out_size) {
    const int*   epoch_p = nullptr;
    const float* xp = nullptr;
    const float* yp = nullptr;
    const int*   hrp = nullptr;
    for (int i = 0; i < n_in; i++) {
        if (in_sizes[i] == 1 && !epoch_p) epoch_p = (const int*)d_in[i];
        else if (in_sizes[i] == BB * NN) { if (!xp) xp = (const float*)d_in[i]; else yp = (const float*)d_in[i]; }
        else if (in_sizes[i] == BB) hrp = (const int*)d_in[i];
    }
    float* out = (float*)d_out;

    k_fold<<<BB, 512>>>(xp, yp);
    k_dft<<<dim3(32, NCH), 288>>>();
    k_loss<<<BB, LT>>>(hrp);
    k_final<<<1, 1024>>>(epoch_p, out);
    (void)out_size;
}